// round 7
// baseline (speedup 1.0000x reference)
#include <cuda_runtime.h>
#include <cuda_fp16.h>
#include <math.h>
#include <stdint.h>

#define N_NODES 100000
#define N_EDGES 640000
#define DIM     128
#define N_GRAPHS 512

#define SCAN_CHUNK 512
#define NB ((N_NODES + SCAN_CHUNK - 1) / SCAN_CHUNK)   // 196

// ---------------- device scratch (allocation-free) ----------------
__device__ __half g_hx[(size_t)N_NODES * DIM];   // fp16 copy of x
__device__ __half g_h1[(size_t)N_NODES * DIM];   // y1 / y3
__device__ __half g_h2[(size_t)N_NODES * DIM];   // y2
__device__ float g_dinv[N_NODES];
__device__ int   g_deg[N_NODES];
__device__ int   g_ptr[N_NODES + 1];
__device__ int   g_cur[N_NODES];
__device__ int2  g_edge[N_EDGES];                // {row, bits(norm)}, CSR order
__device__ int   g_bsum[NB];
__device__ float g_Bhi[DIM * DIM];
__device__ float g_Blo[DIM * DIM];
__device__ float g_z[N_GRAPHS * DIM];

// ---------------- init: deg=0, z=0 ----------------
__global__ void k_init_small() {
    int i = blockIdx.x * blockDim.x + threadIdx.x;
    if (i < N_NODES) g_deg[i] = 0;
    if (i < N_GRAPHS * DIM) g_z[i] = 0.f;
}

__global__ void k_deg(const int* __restrict__ col) {
    int e = blockIdx.x * blockDim.x + threadIdx.x;
    if (e < N_EDGES) atomicAdd(&g_deg[col[e]], 1);
}

// ---------------- convert x -> fp16 ----------------
__global__ void k_convx(const float* __restrict__ x) {
    int i = blockIdx.x * blockDim.x + threadIdx.x;   // one float4 slot
    if (i >= N_NODES * 32) return;
    float4 v = *reinterpret_cast<const float4*>(x + (size_t)i * 4);
    __half2 h0 = __floats2half2_rn(v.x, v.y);
    __half2 h1 = __floats2half2_rn(v.z, v.w);
    uint2 u;
    u.x = *reinterpret_cast<uint32_t*>(&h0);
    u.y = *reinterpret_cast<uint32_t*>(&h1);
    *reinterpret_cast<uint2*>(&g_hx[(size_t)i * 4]) = u;
}

// ---------------- scan pass 1: per-chunk sums + dinv ----------------
__global__ void __launch_bounds__(256) k_scan1() {
    __shared__ int s[256];
    int b = blockIdx.x, t = threadIdx.x;
    int sum = 0;
    #pragma unroll
    for (int l = 0; l < 2; l++) {
        int v = b * SCAN_CHUNK + t + l * 256;
        if (v < N_NODES) {
            int d = g_deg[v];
            g_dinv[v] = rsqrtf((float)(d + 1));
            sum += d;
        }
    }
    s[t] = sum;
    __syncthreads();
    for (int off = 128; off > 0; off >>= 1) {
        if (t < off) s[t] += s[t + off];
        __syncthreads();
    }
    if (t == 0) g_bsum[b] = s[0];
}

// ---------------- scan pass 2 (fused): ptr / cur ----------------
__global__ void __launch_bounds__(SCAN_CHUNK) k_scan3() {
    __shared__ int s[SCAN_CHUNK];
    __shared__ int sb[256];
    int t = threadIdx.x;

    if (t < 256) sb[t] = (t < NB) ? g_bsum[t] : 0;
    __syncthreads();
    for (int off = 1; off < 256; off <<= 1) {
        int tmp = (t < 256 && t >= off) ? sb[t - off] : 0;
        __syncthreads();
        if (t < 256) sb[t] += tmp;
        __syncthreads();
    }
    int boff = (blockIdx.x == 0) ? 0 : sb[blockIdx.x - 1];

    int v = blockIdx.x * SCAN_CHUNK + t;
    int cnt = (v < N_NODES) ? g_deg[v] : 0;
    s[t] = cnt;
    __syncthreads();
    for (int off = 1; off < SCAN_CHUNK; off <<= 1) {
        int tmp = (t >= off) ? s[t - off] : 0;
        __syncthreads();
        s[t] += tmp;
        __syncthreads();
    }
    if (v < N_NODES) {
        int incl = s[t];
        int p = boff + incl - cnt;
        g_ptr[v] = p;
        g_cur[v] = p;
        if (v == N_NODES - 1) g_ptr[N_NODES] = boff + incl;
    }
}

// ---------------- scatter edges into CSR (packed row+norm) ------------
__global__ void k_scatter(const int* __restrict__ row,
                          const int* __restrict__ col) {
    int e = blockIdx.x * blockDim.x + threadIdx.x;
    if (e < N_EDGES) {
        int r = row[e];
        int c = col[e];
        int pos = atomicAdd(&g_cur[c], 1);
        float nrm = g_dinv[r] * g_dinv[c];
        g_edge[pos] = make_int2(r, __float_as_int(nrm));
    }
}

// ---------------- W12 = W0 @ W1, tf32 hi/lo split ----------------
__global__ void __launch_bounds__(128) k_w12split(const float* __restrict__ W0,
                                                  const float* __restrict__ W1) {
    __shared__ float sw0[DIM];
    int i = blockIdx.x, j = threadIdx.x;
    sw0[j] = W0[i * DIM + j];
    __syncthreads();
    float a0 = 0.f, a1 = 0.f, a2 = 0.f, a3 = 0.f;
    #pragma unroll
    for (int k = 0; k < DIM; k += 4) {
        a0 += sw0[k + 0] * W1[(k + 0) * DIM + j];
        a1 += sw0[k + 1] * W1[(k + 1) * DIM + j];
        a2 += sw0[k + 2] * W1[(k + 2) * DIM + j];
        a3 += sw0[k + 3] * W1[(k + 3) * DIM + j];
    }
    float acc = (a0 + a1) + (a2 + a3);
    uint32_t hi;
    asm("cvt.rna.tf32.f32 %0, %1;" : "=r"(hi) : "f"(acc));
    float lof = acc - __uint_as_float(hi);
    uint32_t lo;
    asm("cvt.rna.tf32.f32 %0, %1;" : "=r"(lo) : "f"(lof));
    g_Bhi[i * DIM + j] = __uint_as_float(hi);
    g_Blo[i * DIM + j] = __uint_as_float(lo);
}

// ---------------- unpack 8 halves (uint4) -> 8 floats ----------------
__device__ __forceinline__ void unpack8(const uint4& u, float* f) {
    __half2 h0 = *reinterpret_cast<const __half2*>(&u.x);
    __half2 h1 = *reinterpret_cast<const __half2*>(&u.y);
    __half2 h2 = *reinterpret_cast<const __half2*>(&u.z);
    __half2 h3 = *reinterpret_cast<const __half2*>(&u.w);
    float2 f0 = __half22float2(h0);
    float2 f1 = __half22float2(h1);
    float2 f2 = __half22float2(h2);
    float2 f3 = __half22float2(h3);
    f[0] = f0.x; f[1] = f0.y; f[2] = f1.x; f[3] = f1.y;
    f[4] = f2.x; f[5] = f2.y; f[6] = f3.x; f[7] = f3.y;
}

// ---------------- CSR propagation: warp per node, half-warp pairs -----
// Lanes 0-15 handle even edges, lanes 16-31 odd edges; each gather step
// loads 4 independent rows per lane (uint4 = 8 halves) covering 8 edges.
// MODE 0: src = g_hx -> g_h1
// MODE 1: src = g_h1 -> g_h2
// MODE 2: src = g_h1 -> red.add into g_z[batch[v]]  (fp32)
template <int MODE>
__global__ void __launch_bounds__(256) k_cprop(const int* __restrict__ batch) {
    int gw = (blockIdx.x * blockDim.x + threadIdx.x) >> 5;
    int lane = threadIdx.x & 31;
    if (gw >= N_NODES) return;

    int lane16 = lane & 15;
    int hi = lane >> 4;
    const __half* src = (MODE == 0) ? g_hx : g_h1;
    float dv = g_dinv[gw];

    float acc[8];
    {   // self loop: only half 0 contributes
        uint4 u = *reinterpret_cast<const uint4*>(
                      src + (size_t)gw * DIM + lane16 * 8);
        float f[8];
        unpack8(u, f);
        float s = (hi == 0) ? dv * dv : 0.f;
        #pragma unroll
        for (int k = 0; k < 8; k++) acc[k] = f[k] * s;
    }

    int beg = g_ptr[gw], end = g_ptr[gw + 1];
    for (int base = beg; base < end; base += 32) {
        int idx = base + lane;
        int r = 0;
        float nrm = 0.f;
        if (idx < end) {
            int2 e = g_edge[idx];
            r = e.x;
            nrm = __int_as_float(e.y);
        }
        int cnt = min(32, end - base);
        int npairs = (cnt + 1) >> 1;
        for (int j = 0; j < npairs; j += 4) {
            int rr[4];
            float nn[4];
            #pragma unroll
            for (int q = 0; q < 4; q++) {
                int sidx = 2 * (j + q) + hi;
                int cl = min(sidx, cnt - 1);
                rr[q] = __shfl_sync(0xffffffffu, r, cl);
                float w = __shfl_sync(0xffffffffu, nrm, cl);
                nn[q] = (sidx < cnt) ? w : 0.f;
            }
            uint4 xv[4];
            #pragma unroll
            for (int q = 0; q < 4; q++)
                xv[q] = *reinterpret_cast<const uint4*>(
                            src + (size_t)rr[q] * DIM + lane16 * 8);
            #pragma unroll
            for (int q = 0; q < 4; q++) {
                float f[8];
                unpack8(xv[q], f);
                #pragma unroll
                for (int k = 0; k < 8; k++) acc[k] += nn[q] * f[k];
            }
        }
    }

    // cross-half reduction: add odd-edge half into even half
    #pragma unroll
    for (int k = 0; k < 8; k++)
        acc[k] += __shfl_xor_sync(0xffffffffu, acc[k], 16);

    if (hi == 0) {
        if (MODE == 2) {
            float* dst = g_z + (size_t)batch[gw] * DIM + lane16 * 8;
            asm volatile("red.global.add.v4.f32 [%0], {%1, %2, %3, %4};"
                         :: "l"(dst), "f"(acc[0]), "f"(acc[1]),
                            "f"(acc[2]), "f"(acc[3]) : "memory");
            asm volatile("red.global.add.v4.f32 [%0], {%1, %2, %3, %4};"
                         :: "l"(dst + 4), "f"(acc[4]), "f"(acc[5]),
                            "f"(acc[6]), "f"(acc[7]) : "memory");
        } else {
            __half* dstb = (MODE == 0) ? g_h1 : g_h2;
            __half2 o0 = __floats2half2_rn(acc[0], acc[1]);
            __half2 o1 = __floats2half2_rn(acc[2], acc[3]);
            __half2 o2 = __floats2half2_rn(acc[4], acc[5]);
            __half2 o3 = __floats2half2_rn(acc[6], acc[7]);
            uint4 u;
            u.x = *reinterpret_cast<uint32_t*>(&o0);
            u.y = *reinterpret_cast<uint32_t*>(&o1);
            u.z = *reinterpret_cast<uint32_t*>(&o2);
            u.w = *reinterpret_cast<uint32_t*>(&o3);
            *reinterpret_cast<uint4*>(dstb + (size_t)gw * DIM + lane16 * 8) = u;
        }
    }
}

// ---------------- y3 = leaky_relu(y2 @ W12) -> g_h1 (tf32, 2 MMA) -----
#define GK 16
#define SA_STRIDE 20
#define SB_STRIDE 136

__device__ __forceinline__ void mma_tf32(float* c, const uint32_t* a,
                                         const uint32_t* b) {
    asm volatile(
        "mma.sync.aligned.m16n8k8.row.col.f32.tf32.tf32.f32 "
        "{%0,%1,%2,%3}, {%4,%5,%6,%7}, {%8,%9}, {%0,%1,%2,%3};"
        : "+f"(c[0]), "+f"(c[1]), "+f"(c[2]), "+f"(c[3])
        : "r"(a[0]), "r"(a[1]), "r"(a[2]), "r"(a[3]), "r"(b[0]), "r"(b[1]));
}

__global__ void __launch_bounds__(256) k_gemm_tc() {
    __shared__ float sA[128 * SA_STRIDE];
    __shared__ float sBhi[GK * SB_STRIDE];
    __shared__ float sBlo[GK * SB_STRIDE];

    int t = threadIdx.x;
    int warp = t >> 5, lane = t & 31;
    int wm = warp >> 2, wn = warp & 3;
    int group = lane >> 2, tg = lane & 3;
    int i0 = blockIdx.x * 128;

    float acc[4][4][4];
    #pragma unroll
    for (int a = 0; a < 4; a++)
        #pragma unroll
        for (int b = 0; b < 4; b++)
            #pragma unroll
            for (int c = 0; c < 4; c++) acc[a][b][c] = 0.f;

    for (int k0 = 0; k0 < DIM; k0 += GK) {
        #pragma unroll
        for (int l = 0; l < 2; l++) {
            int q = t + l * 256;
            int rrow = q >> 2;
            int kq = (q & 3) * 4;
            float4 v = make_float4(0.f, 0.f, 0.f, 0.f);
            int gr = i0 + rrow;
            if (gr < N_NODES) {
                uint2 u = *reinterpret_cast<const uint2*>(
                              &g_h2[(size_t)gr * DIM + k0 + kq]);
                __half2 h0 = *reinterpret_cast<__half2*>(&u.x);
                __half2 h1 = *reinterpret_cast<__half2*>(&u.y);
                float2 f0 = __half22float2(h0);
                float2 f1 = __half22float2(h1);
                v = make_float4(f0.x, f0.y, f1.x, f1.y);
            }
            *reinterpret_cast<float4*>(&sA[rrow * SA_STRIDE + kq]) = v;
        }
        #pragma unroll
        for (int l = 0; l < 2; l++) {
            int q = t + l * 256;
            int kr = q >> 5;
            int n4 = (q & 31) * 4;
            *reinterpret_cast<float4*>(&sBhi[kr * SB_STRIDE + n4]) =
                *reinterpret_cast<const float4*>(&g_Bhi[(k0 + kr) * DIM + n4]);
            *reinterpret_cast<float4*>(&sBlo[kr * SB_STRIDE + n4]) =
                *reinterpret_cast<const float4*>(&g_Blo[(k0 + kr) * DIM + n4]);
        }
        __syncthreads();

        #pragma unroll
        for (int kk = 0; kk < GK / 8; kk++) {
            int kb = kk * 8;
            uint32_t bh[4][2], bl[4][2];
            #pragma unroll
            for (int nn = 0; nn < 4; nn++) {
                int n = wn * 32 + nn * 8 + group;
                bh[nn][0] = __float_as_uint(sBhi[(kb + tg) * SB_STRIDE + n]);
                bh[nn][1] = __float_as_uint(sBhi[(kb + tg + 4) * SB_STRIDE + n]);
                bl[nn][0] = __float_as_uint(sBlo[(kb + tg) * SB_STRIDE + n]);
                bl[nn][1] = __float_as_uint(sBlo[(kb + tg + 4) * SB_STRIDE + n]);
            }
            uint32_t ah[4][4];
            #pragma unroll
            for (int mm = 0; mm < 4; mm++) {
                int r0 = wm * 64 + mm * 16 + group;
                #pragma unroll
                for (int e = 0; e < 4; e++) {
                    int rr = r0 + ((e & 1) ? 8 : 0);
                    int cc = kb + tg + ((e & 2) ? 4 : 0);
                    float a = sA[rr * SA_STRIDE + cc];
                    uint32_t hi;
                    asm("cvt.rna.tf32.f32 %0, %1;" : "=r"(hi) : "f"(a));
                    ah[mm][e] = hi;
                }
            }
            #pragma unroll
            for (int mm = 0; mm < 4; mm++)
                #pragma unroll
                for (int nn = 0; nn < 4; nn++) {
                    mma_tf32(acc[mm][nn], ah[mm], bh[nn]);
                    mma_tf32(acc[mm][nn], ah[mm], bl[nn]);
                }
        }
        __syncthreads();
    }

    #pragma unroll
    for (int mm = 0; mm < 4; mm++) {
        #pragma unroll
        for (int nn = 0; nn < 4; nn++) {
            int colb = wn * 32 + nn * 8 + tg * 2;
            #pragma unroll
            for (int half = 0; half < 2; half++) {
                int rr = i0 + wm * 64 + mm * 16 + group + half * 8;
                if (rr < N_NODES) {
                    float v0 = acc[mm][nn][half * 2 + 0];
                    float v1 = acc[mm][nn][half * 2 + 1];
                    v0 = (v0 > 0.f) ? v0 : 0.01f * v0;
                    v1 = (v1 > 0.f) ? v1 : 0.01f * v1;
                    __half2 hv = __floats2half2_rn(v0, v1);
                    *reinterpret_cast<__half2*>(
                        &g_h1[(size_t)rr * DIM + colb]) = hv;
                }
            }
        }
    }
}

// ---------------- out = g_z @ W2 (fp32) ----------------
__global__ void k_out(const float* __restrict__ W2, float* __restrict__ out) {
    __shared__ float sz[DIM];
    int g = blockIdx.x;
    int j = threadIdx.x;
    sz[j] = g_z[g * DIM + j];
    __syncthreads();
    float acc = 0.f;
    #pragma unroll 8
    for (int k = 0; k < DIM; k++)
        acc += sz[k] * W2[k * DIM + j];
    out[g * DIM + j] = acc;
}

// ---------------- launch ----------------
extern "C" void kernel_launch(void* const* d_in, const int* in_sizes, int n_in,
                              void* d_out, int out_size) {
    const float* x     = (const float*)d_in[0];
    const int*   ei    = (const int*)d_in[1];
    const int*   batch = (const int*)d_in[2];
    const float* W0    = (const float*)d_in[3];
    const float* W1    = (const float*)d_in[4];
    const float* W2    = (const float*)d_in[5];
    float* out = (float*)d_out;

    const int* row = ei;
    const int* col = ei + N_EDGES;

    k_init_small<<<(N_NODES + 255) / 256, 256>>>();
    k_deg<<<(N_EDGES + 255) / 256, 256>>>(col);
    k_convx<<<(N_NODES * 32 + 255) / 256, 256>>>(x);
    k_scan1<<<NB, 256>>>();
    k_scan3<<<NB, SCAN_CHUNK>>>();
    k_scatter<<<(N_EDGES + 255) / 256, 256>>>(row, col);
    k_w12split<<<DIM, DIM>>>(W0, W1);

    int pblocks = (N_NODES * 32 + 255) / 256;

    k_cprop<0><<<pblocks, 256>>>(batch);           // y1 = Â x      (fp16)
    k_cprop<1><<<pblocks, 256>>>(batch);           // y2 = Â y1     (fp16)
    k_gemm_tc<<<(N_NODES + 127) / 128, 256>>>();   // y3 = leaky(y2@W12)
    k_cprop<2><<<pblocks, 256>>>(batch);           // z = P Â y3    (fp32)
    k_out<<<N_GRAPHS, DIM>>>(W2, out);
}

// round 8
// speedup vs baseline: 1.1887x; 1.1887x over previous
#include <cuda_runtime.h>
#include <cuda_fp16.h>
#include <math.h>
#include <stdint.h>

#define N_NODES 100000
#define N_EDGES 640000
#define DIM     128
#define N_GRAPHS 512

#define SCAN_CHUNK 512
#define NB ((N_NODES + SCAN_CHUNK - 1) / SCAN_CHUNK)   // 196

// ---------------- device scratch (allocation-free) ----------------
__device__ __half g_hx[(size_t)N_NODES * DIM];   // fp16 copy of x
__device__ __half g_h1[(size_t)N_NODES * DIM];   // y1 / y3
__device__ __half g_h2[(size_t)N_NODES * DIM];   // y2
__device__ float g_dinv[N_NODES];
__device__ int   g_deg[N_NODES];
__device__ int   g_ptr[N_NODES + 1];
__device__ int   g_cur[N_NODES];
__device__ int2  g_edge[N_EDGES];                // {row, bits(norm)}, CSR order
__device__ int   g_bsum[NB];
__device__ float g_Bhi[DIM * DIM];
__device__ float g_Blo[DIM * DIM];
__device__ float g_z[N_GRAPHS * DIM];

// ---------------- prep: convert x -> fp16, zero deg & z ----------------
__global__ void k_prep(const float* __restrict__ x) {
    int i = blockIdx.x * blockDim.x + threadIdx.x;   // one float4 slot
    if (i < N_NODES * 32) {
        float4 v = *reinterpret_cast<const float4*>(x + (size_t)i * 4);
        __half2 h0 = __floats2half2_rn(v.x, v.y);
        __half2 h1 = __floats2half2_rn(v.z, v.w);
        uint2 u;
        u.x = *reinterpret_cast<uint32_t*>(&h0);
        u.y = *reinterpret_cast<uint32_t*>(&h1);
        *reinterpret_cast<uint2*>(&g_hx[(size_t)i * 4]) = u;
    }
    if (i < N_NODES) g_deg[i] = 0;
    if (i < N_GRAPHS * DIM) g_z[i] = 0.f;
}

__global__ void k_deg(const int* __restrict__ col) {
    int e = blockIdx.x * blockDim.x + threadIdx.x;
    if (e < N_EDGES) atomicAdd(&g_deg[col[e]], 1);
}

// ---------------- scan pass 1: per-chunk sums + dinv ----------------
__global__ void __launch_bounds__(256) k_scan1() {
    __shared__ int s[256];
    int b = blockIdx.x, t = threadIdx.x;
    int sum = 0;
    #pragma unroll
    for (int l = 0; l < 2; l++) {
        int v = b * SCAN_CHUNK + t + l * 256;
        if (v < N_NODES) {
            int d = g_deg[v];
            g_dinv[v] = rsqrtf((float)(d + 1));
            sum += d;
        }
    }
    s[t] = sum;
    __syncthreads();
    for (int off = 128; off > 0; off >>= 1) {
        if (t < off) s[t] += s[t + off];
        __syncthreads();
    }
    if (t == 0) g_bsum[b] = s[0];
}

// ---------------- scan pass 2 (fused): ptr / cur ----------------
__global__ void __launch_bounds__(SCAN_CHUNK) k_scan3() {
    __shared__ int s[SCAN_CHUNK];
    __shared__ int sb[256];
    int t = threadIdx.x;

    if (t < 256) sb[t] = (t < NB) ? g_bsum[t] : 0;
    __syncthreads();
    for (int off = 1; off < 256; off <<= 1) {
        int tmp = (t < 256 && t >= off) ? sb[t - off] : 0;
        __syncthreads();
        if (t < 256) sb[t] += tmp;
        __syncthreads();
    }
    int boff = (blockIdx.x == 0) ? 0 : sb[blockIdx.x - 1];

    int v = blockIdx.x * SCAN_CHUNK + t;
    int cnt = (v < N_NODES) ? g_deg[v] : 0;
    s[t] = cnt;
    __syncthreads();
    for (int off = 1; off < SCAN_CHUNK; off <<= 1) {
        int tmp = (t >= off) ? s[t - off] : 0;
        __syncthreads();
        s[t] += tmp;
        __syncthreads();
    }
    if (v < N_NODES) {
        int incl = s[t];
        int p = boff + incl - cnt;
        g_ptr[v] = p;
        g_cur[v] = p;
        if (v == N_NODES - 1) g_ptr[N_NODES] = boff + incl;
    }
}

// ---------------- scatter edges into CSR (packed row+norm) ------------
__global__ void k_scatter(const int* __restrict__ row,
                          const int* __restrict__ col) {
    int e = blockIdx.x * blockDim.x + threadIdx.x;
    if (e < N_EDGES) {
        int r = row[e];
        int c = col[e];
        int pos = atomicAdd(&g_cur[c], 1);
        float nrm = g_dinv[r] * g_dinv[c];
        g_edge[pos] = make_int2(r, __float_as_int(nrm));
    }
}

// ---------------- W12 = W0 @ W1, tf32 hi/lo split ----------------
__global__ void __launch_bounds__(128) k_w12split(const float* __restrict__ W0,
                                                  const float* __restrict__ W1) {
    __shared__ float sw0[DIM];
    int i = blockIdx.x, j = threadIdx.x;
    sw0[j] = W0[i * DIM + j];
    __syncthreads();
    float a0 = 0.f, a1 = 0.f, a2 = 0.f, a3 = 0.f;
    #pragma unroll
    for (int k = 0; k < DIM; k += 4) {
        a0 += sw0[k + 0] * W1[(k + 0) * DIM + j];
        a1 += sw0[k + 1] * W1[(k + 1) * DIM + j];
        a2 += sw0[k + 2] * W1[(k + 2) * DIM + j];
        a3 += sw0[k + 3] * W1[(k + 3) * DIM + j];
    }
    float acc = (a0 + a1) + (a2 + a3);
    uint32_t hi;
    asm("cvt.rna.tf32.f32 %0, %1;" : "=r"(hi) : "f"(acc));
    float lof = acc - __uint_as_float(hi);
    uint32_t lo;
    asm("cvt.rna.tf32.f32 %0, %1;" : "=r"(lo) : "f"(lof));
    g_Bhi[i * DIM + j] = __uint_as_float(hi);
    g_Blo[i * DIM + j] = __uint_as_float(lo);
}

// ---------------- fp16 gather helper ----------------
__device__ __forceinline__ float4 ld_row_h4(const __half* src, int r, int lane) {
    uint2 u = *reinterpret_cast<const uint2*>(src + (size_t)r * DIM + lane * 4);
    __half2 h0 = *reinterpret_cast<__half2*>(&u.x);
    __half2 h1 = *reinterpret_cast<__half2*>(&u.y);
    float2 f0 = __half22float2(h0);
    float2 f1 = __half22float2(h1);
    return make_float4(f0.x, f0.y, f1.x, f1.y);
}

// ---------------- CSR propagation: warp per node, MLP-4, no tail ------
// R6 loop shape/registers, but the MLP-4 step is predicated: overrun
// slots clamp to the last valid edge (same-line gather) with weight 0.
// MODE 0: src = g_hx -> g_h1
// MODE 1: src = g_h1 -> g_h2
// MODE 2: src = g_h1 -> red.add into g_z[batch[v]]  (fp32)
template <int MODE>
__global__ void __launch_bounds__(256) k_cprop(const int* __restrict__ batch) {
    int gw = (blockIdx.x * blockDim.x + threadIdx.x) >> 5;
    int lane = threadIdx.x & 31;
    if (gw >= N_NODES) return;

    const __half* src = (MODE == 0) ? g_hx : g_h1;
    float dv = g_dinv[gw];

    float4 a = ld_row_h4(src, gw, lane);
    float s = dv * dv;
    float4 acc = make_float4(a.x * s, a.y * s, a.z * s, a.w * s);

    int beg = g_ptr[gw], end = g_ptr[gw + 1];
    for (int base = beg; base < end; base += 32) {
        int idx = base + lane;
        int r = 0;
        float nrm = 0.f;
        if (idx < end) {
            int2 e = g_edge[idx];
            r = e.x;
            nrm = __int_as_float(e.y);
        }
        int cnt = min(32, end - base);
        int last = cnt - 1;
        for (int i = 0; i < cnt; i += 4) {
            int c1 = min(i + 1, last);
            int c2 = min(i + 2, last);
            int c3 = min(i + 3, last);
            int r0 = __shfl_sync(0xffffffffu, r, i);
            int r1 = __shfl_sync(0xffffffffu, r, c1);
            int r2 = __shfl_sync(0xffffffffu, r, c2);
            int r3 = __shfl_sync(0xffffffffu, r, c3);
            float n0 = __shfl_sync(0xffffffffu, nrm, i);
            float n1 = __shfl_sync(0xffffffffu, nrm, c1);
            float n2 = __shfl_sync(0xffffffffu, nrm, c2);
            float n3 = __shfl_sync(0xffffffffu, nrm, c3);
            n1 = (i + 1 < cnt) ? n1 : 0.f;
            n2 = (i + 2 < cnt) ? n2 : 0.f;
            n3 = (i + 3 < cnt) ? n3 : 0.f;
            float4 x0 = ld_row_h4(src, r0, lane);
            float4 x1 = ld_row_h4(src, r1, lane);
            float4 x2 = ld_row_h4(src, r2, lane);
            float4 x3 = ld_row_h4(src, r3, lane);
            acc.x += n0 * x0.x; acc.y += n0 * x0.y;
            acc.z += n0 * x0.z; acc.w += n0 * x0.w;
            acc.x += n1 * x1.x; acc.y += n1 * x1.y;
            acc.z += n1 * x1.z; acc.w += n1 * x1.w;
            acc.x += n2 * x2.x; acc.y += n2 * x2.y;
            acc.z += n2 * x2.z; acc.w += n2 * x2.w;
            acc.x += n3 * x3.x; acc.y += n3 * x3.y;
            acc.z += n3 * x3.z; acc.w += n3 * x3.w;
        }
    }

    if (MODE == 2) {
        float* dst = g_z + (size_t)batch[gw] * DIM + lane * 4;
        asm volatile("red.global.add.v4.f32 [%0], {%1, %2, %3, %4};"
                     :: "l"(dst), "f"(acc.x), "f"(acc.y), "f"(acc.z), "f"(acc.w)
                     : "memory");
    } else {
        __half* dstb = (MODE == 0) ? g_h1 : g_h2;
        __half2 o0 = __floats2half2_rn(acc.x, acc.y);
        __half2 o1 = __floats2half2_rn(acc.z, acc.w);
        uint2 u;
        u.x = *reinterpret_cast<uint32_t*>(&o0);
        u.y = *reinterpret_cast<uint32_t*>(&o1);
        *reinterpret_cast<uint2*>(dstb + (size_t)gw * DIM + lane * 4) = u;
    }
}

// ---------------- y3 = leaky_relu(y2 @ W12) -> g_h1 (tf32, 2 MMA) -----
#define GK 16
#define SA_STRIDE 20
#define SB_STRIDE 136

__device__ __forceinline__ void mma_tf32(float* c, const uint32_t* a,
                                         const uint32_t* b) {
    asm volatile(
        "mma.sync.aligned.m16n8k8.row.col.f32.tf32.tf32.f32 "
        "{%0,%1,%2,%3}, {%4,%5,%6,%7}, {%8,%9}, {%0,%1,%2,%3};"
        : "+f"(c[0]), "+f"(c[1]), "+f"(c[2]), "+f"(c[3])
        : "r"(a[0]), "r"(a[1]), "r"(a[2]), "r"(a[3]), "r"(b[0]), "r"(b[1]));
}

__global__ void __launch_bounds__(256) k_gemm_tc() {
    __shared__ float sA[128 * SA_STRIDE];
    __shared__ float sBhi[GK * SB_STRIDE];
    __shared__ float sBlo[GK * SB_STRIDE];

    int t = threadIdx.x;
    int warp = t >> 5, lane = t & 31;
    int wm = warp >> 2, wn = warp & 3;
    int group = lane >> 2, tg = lane & 3;
    int i0 = blockIdx.x * 128;

    float acc[4][4][4];
    #pragma unroll
    for (int a = 0; a < 4; a++)
        #pragma unroll
        for (int b = 0; b < 4; b++)
            #pragma unroll
            for (int c = 0; c < 4; c++) acc[a][b][c] = 0.f;

    for (int k0 = 0; k0 < DIM; k0 += GK) {
        #pragma unroll
        for (int l = 0; l < 2; l++) {
            int q = t + l * 256;
            int rrow = q >> 2;
            int kq = (q & 3) * 4;
            float4 v = make_float4(0.f, 0.f, 0.f, 0.f);
            int gr = i0 + rrow;
            if (gr < N_NODES) {
                uint2 u = *reinterpret_cast<const uint2*>(
                              &g_h2[(size_t)gr * DIM + k0 + kq]);
                __half2 h0 = *reinterpret_cast<__half2*>(&u.x);
                __half2 h1 = *reinterpret_cast<__half2*>(&u.y);
                float2 f0 = __half22float2(h0);
                float2 f1 = __half22float2(h1);
                v = make_float4(f0.x, f0.y, f1.x, f1.y);
            }
            *reinterpret_cast<float4*>(&sA[rrow * SA_STRIDE + kq]) = v;
        }
        #pragma unroll
        for (int l = 0; l < 2; l++) {
            int q = t + l * 256;
            int kr = q >> 5;
            int n4 = (q & 31) * 4;
            *reinterpret_cast<float4*>(&sBhi[kr * SB_STRIDE + n4]) =
                *reinterpret_cast<const float4*>(&g_Bhi[(k0 + kr) * DIM + n4]);
            *reinterpret_cast<float4*>(&sBlo[kr * SB_STRIDE + n4]) =
                *reinterpret_cast<const float4*>(&g_Blo[(k0 + kr) * DIM + n4]);
        }
        __syncthreads();

        #pragma unroll
        for (int kk = 0; kk < GK / 8; kk++) {
            int kb = kk * 8;
            uint32_t bh[4][2], bl[4][2];
            #pragma unroll
            for (int nn = 0; nn < 4; nn++) {
                int n = wn * 32 + nn * 8 + group;
                bh[nn][0] = __float_as_uint(sBhi[(kb + tg) * SB_STRIDE + n]);
                bh[nn][1] = __float_as_uint(sBhi[(kb + tg + 4) * SB_STRIDE + n]);
                bl[nn][0] = __float_as_uint(sBlo[(kb + tg) * SB_STRIDE + n]);
                bl[nn][1] = __float_as_uint(sBlo[(kb + tg + 4) * SB_STRIDE + n]);
            }
            uint32_t ah[4][4];
            #pragma unroll
            for (int mm = 0; mm < 4; mm++) {
                int r0 = wm * 64 + mm * 16 + group;
                #pragma unroll
                for (int e = 0; e < 4; e++) {
                    int rr = r0 + ((e & 1) ? 8 : 0);
                    int cc = kb + tg + ((e & 2) ? 4 : 0);
                    float a = sA[rr * SA_STRIDE + cc];
                    uint32_t hi;
                    asm("cvt.rna.tf32.f32 %0, %1;" : "=r"(hi) : "f"(a));
                    ah[mm][e] = hi;
                }
            }
            #pragma unroll
            for (int mm = 0; mm < 4; mm++)
                #pragma unroll
                for (int nn = 0; nn < 4; nn++) {
                    mma_tf32(acc[mm][nn], ah[mm], bh[nn]);
                    mma_tf32(acc[mm][nn], ah[mm], bl[nn]);
                }
        }
        __syncthreads();
    }

    #pragma unroll
    for (int mm = 0; mm < 4; mm++) {
        #pragma unroll
        for (int nn = 0; nn < 4; nn++) {
            int colb = wn * 32 + nn * 8 + tg * 2;
            #pragma unroll
            for (int half = 0; half < 2; half++) {
                int rr = i0 + wm * 64 + mm * 16 + group + half * 8;
                if (rr < N_NODES) {
                    float v0 = acc[mm][nn][half * 2 + 0];
                    float v1 = acc[mm][nn][half * 2 + 1];
                    v0 = (v0 > 0.f) ? v0 : 0.01f * v0;
                    v1 = (v1 > 0.f) ? v1 : 0.01f * v1;
                    __half2 hv = __floats2half2_rn(v0, v1);
                    *reinterpret_cast<__half2*>(
                        &g_h1[(size_t)rr * DIM + colb]) = hv;
                }
            }
        }
    }
}

// ---------------- out = g_z @ W2 (fp32) ----------------
__global__ void k_out(const float* __restrict__ W2, float* __restrict__ out) {
    __shared__ float sz[DIM];
    int g = blockIdx.x;
    int j = threadIdx.x;
    sz[j] = g_z[g * DIM + j];
    __syncthreads();
    float acc = 0.f;
    #pragma unroll 8
    for (int k = 0; k < DIM; k++)
        acc += sz[k] * W2[k * DIM + j];
    out[g * DIM + j] = acc;
}

// ---------------- launch ----------------
extern "C" void kernel_launch(void* const* d_in, const int* in_sizes, int n_in,
                              void* d_out, int out_size) {
    const float* x     = (const float*)d_in[0];
    const int*   ei    = (const int*)d_in[1];
    const int*   batch = (const int*)d_in[2];
    const float* W0    = (const float*)d_in[3];
    const float* W1    = (const float*)d_in[4];
    const float* W2    = (const float*)d_in[5];
    float* out = (float*)d_out;

    const int* row = ei;
    const int* col = ei + N_EDGES;

    k_prep<<<(N_NODES * 32 + 255) / 256, 256>>>(x);   // convx + zero deg/z
    k_deg<<<(N_EDGES + 255) / 256, 256>>>(col);
    k_scan1<<<NB, 256>>>();
    k_scan3<<<NB, SCAN_CHUNK>>>();
    k_scatter<<<(N_EDGES + 255) / 256, 256>>>(row, col);
    k_w12split<<<DIM, DIM>>>(W0, W1);

    int pblocks = (N_NODES * 32 + 255) / 256;

    k_cprop<0><<<pblocks, 256>>>(batch);           // y1 = Â x      (fp16)
    k_cprop<1><<<pblocks, 256>>>(batch);           // y2 = Â y1     (fp16)
    k_gemm_tc<<<(N_NODES + 127) / 128, 256>>>();   // y3 = leaky(y2@W12)
    k_cprop<2><<<pblocks, 256>>>(batch);           // z = P Â y3    (fp32)
    k_out<<<N_GRAPHS, DIM>>>(W2, out);
}